// round 4
// baseline (speedup 1.0000x reference)
#include <cuda_runtime.h>
#include <math.h>
#include <stdint.h>
#include <float.h>

#define LNUM 2
#define HID 512
#define TMAX 20
#define VOC 10000
#define BAT 32
#define SPA 49
#define G4 2048
#define KXH 1024
#define VLD 10240
#define NVT 20      // v-tiles of 512 (256 pairs)

typedef unsigned long long u64;

// ---------------- f32x2 helpers (sm_103a packed fp32) ----------------
__device__ __forceinline__ u64 ffma2(u64 a, u64 b, u64 c) {
    u64 d; asm("fma.rn.f32x2 %0, %1, %2, %3;" : "=l"(d) : "l"(a), "l"(b), "l"(c)); return d;
}
__device__ __forceinline__ u64 fadd2(u64 a, u64 b) {
    u64 d; asm("add.rn.f32x2 %0, %1, %2;" : "=l"(d) : "l"(a), "l"(b)); return d;
}
__device__ __forceinline__ u64 dup2(float x) {
    u64 d; unsigned u = __float_as_uint(x);
    asm("mov.b64 %0, {%1, %2};" : "=l"(d) : "r"(u), "r"(u)); return d;
}
__device__ __forceinline__ u64 pack2(float x, float y) {
    u64 d; unsigned a = __float_as_uint(x), b = __float_as_uint(y);
    asm("mov.b64 %0, {%1, %2};" : "=l"(d) : "r"(a), "r"(b)); return d;
}
__device__ __forceinline__ float lo2(u64 v) { return __uint_as_float((unsigned)v); }
__device__ __forceinline__ float hi2(u64 v) { return __uint_as_float((unsigned)(v >> 32)); }

// ---------------- static device scratch ----------------
__device__ float d_WcT[LNUM][KXH][G4];        // [l][k][n]  n over 4 gates
__device__ float d_WqT[HID][HID];             // [k][d]
__device__ float d_hattWT[KXH][HID];          // [k][j]
__device__ float d_projWT[HID][VLD];          // [k][v] padded (pad stays 0)
__device__ float d_keys[BAT][SPA][HID];
__device__ float d_vals[BAT][SPA][HID];
__device__ float d_hA[LNUM][BAT][HID];        // h entering a step
__device__ float d_hB[LNUM][BAT][HID];        // post-LSTM h
__device__ float d_cst[LNUM][BAT][HID];
__device__ float d_ah[LNUM*BAT][KXH];         // [attn | hB]
__device__ float d_P1[16][BAT][G4];           // LSTM partials (ksplit 16)
__device__ float d_P2[8][BAT][VLD];           // proj partials (ksplit 8)
__device__ float d_logits[TMAX][BAT][VOC];
__device__ float d_tmax[BAT][NVT];
__device__ int   d_tidx[BAT][NVT];
__device__ int   d_best[BAT];

// ---------------- tiled transpose: out[c][r] = in[r][c] ----------------
__global__ void transpose_k(const float* __restrict__ in, float* __restrict__ out,
                            int R, int C, int oLd) {
    __shared__ float tile[32][33];
    int c0 = blockIdx.x * 32, r0 = blockIdx.y * 32;
    int x = threadIdx.x;
    for (int y = threadIdx.y; y < 32; y += 8) {
        int r = r0 + y, c = c0 + x;
        tile[y][x] = (r < R && c < C) ? in[(size_t)r * C + c] : 0.f;
    }
    __syncthreads();
    for (int y = threadIdx.y; y < 32; y += 8) {
        int c = c0 + y, r = r0 + x;
        if (c < C && r < R) out[(size_t)c * oLd + r] = tile[x][y];
    }
}

// ---------------- f32x2 B-streamed GEMM partial ----------------
// A rows m<32: k<512 from (gather ? embed[best[m]] : Alo[m]), k>=512 from Ahi[m].
// Bt k-major [K][2*ldn2 floats]; each thread owns one f32x2 column pair over KC k's.
// P[ksplit][32][2*npTot floats] f32x2 partials.
template<int KC>
__global__ void __launch_bounds__(128) gemm2(
    const float* __restrict__ Alo, const float* __restrict__ Ahi,
    const float* __restrict__ embed, const int* __restrict__ best,
    const float* __restrict__ Bt, int ldn2,
    float* __restrict__ P, int npTot)
{
    __shared__ u64 As2[KC][32];
    __shared__ int sbest[32];
    int tid = threadIdx.x;
    int k0 = blockIdx.y * KC;
    if (embed && tid < 32) sbest[tid] = best[tid];
    __syncthreads();
    for (int i = tid; i < 32 * KC; i += 128) {
        int m = i / KC, kk = i % KC, k = k0 + kk;
        float a;
        if (k < 512) a = embed ? embed[(size_t)sbest[m] * HID + k] : Alo[m * HID + k];
        else         a = Ahi[m * HID + (k - 512)];
        As2[kk][m] = dup2(a);
    }
    __syncthreads();
    int npair = blockIdx.x * 128 + tid;
    const u64* Bp = (const u64*)Bt;
    u64 acc[32];
#pragma unroll
    for (int m = 0; m < 32; m++) acc[m] = 0ull;
#pragma unroll 4
    for (int kk = 0; kk < KC; kk++) {
        u64 bv = __ldg(Bp + (size_t)(k0 + kk) * ldn2 + npair);
#pragma unroll
        for (int m = 0; m < 32; m++) acc[m] = ffma2(As2[kk][m], bv, acc[m]);
    }
    u64* Pu = (u64*)P;
    int rb = blockIdx.y * 32;
#pragma unroll
    for (int m = 0; m < 32; m++) Pu[(size_t)(rb + m) * npTot + npair] = acc[m];
}

// ---------------- LSTM epilogue: reduce 16 partials, activate ----------------
__global__ void lstm_act2(int l, const float* __restrict__ bih, const float* __restrict__ bhh) {
    int b = blockIdx.x, jp = threadIdx.x;           // 32 blocks x 256 thr; jp = j-pair
    const u64* Pu = (const u64*)d_P1;
    u64 g2[4];
#pragma unroll
    for (int gi = 0; gi < 4; gi++) {
        u64 s = 0ull;
        int col = gi * 256 + jp;
#pragma unroll
        for (int ks = 0; ks < 16; ks++) s = fadd2(s, Pu[(size_t)(ks * 32 + b) * 1024 + col]);
        u64 bi = *(const u64*)(bih + l * G4 + gi * HID + 2 * jp);
        u64 bh = *(const u64*)(bhh + l * G4 + gi * HID + 2 * jp);
        g2[gi] = fadd2(s, fadd2(bi, bh));
    }
    u64 cold = *(const u64*)&d_cst[l][b][2 * jp];
    float hlo, hhi, clo, chi;
    {
        float i_ = 1.f / (1.f + expf(-lo2(g2[0])));
        float f_ = 1.f / (1.f + expf(-lo2(g2[1])));
        float gg = tanhf(lo2(g2[2]));
        float o_ = 1.f / (1.f + expf(-lo2(g2[3])));
        clo = f_ * lo2(cold) + i_ * gg;
        hlo = o_ * tanhf(clo);
    }
    {
        float i_ = 1.f / (1.f + expf(-hi2(g2[0])));
        float f_ = 1.f / (1.f + expf(-hi2(g2[1])));
        float gg = tanhf(hi2(g2[2]));
        float o_ = 1.f / (1.f + expf(-hi2(g2[3])));
        chi = f_ * hi2(cold) + i_ * gg;
        hhi = o_ * tanhf(chi);
    }
    *(u64*)&d_cst[l][b][2 * jp] = pack2(clo, chi);
    *(u64*)&d_hB[l][b][2 * jp]  = pack2(hlo, hhi);
    *(u64*)&d_ah[l * BAT + b][HID + 2 * jp] = pack2(hlo, hhi);
}

// ---------------- proj combine: logits + per-tile (max, idx) ----------------
__global__ void proj_combine2(int t, const float* __restrict__ projb) {
    int b = blockIdx.y, tid = threadIdx.x;
    int vp = blockIdx.x * 256 + tid;                // pair index
    const u64* Pu = (const u64*)d_P2;
    u64 s = 0ull;
#pragma unroll
    for (int ks = 0; ks < 8; ks++) s = fadd2(s, Pu[(size_t)(ks * 32 + b) * 5120 + vp]);
    float val = -FLT_MAX; int idx = 0x7fffffff;
    if (vp < 5000) {
        s = fadd2(s, *(const u64*)(projb + 2 * vp));
        *(u64*)&d_logits[t][b][2 * vp] = s;
        float l = lo2(s), h = hi2(s);
        if (h > l) { val = h; idx = 2 * vp + 1; } else { val = l; idx = 2 * vp; }
    }
    __shared__ float sm[256];
    __shared__ int si[256];
    sm[tid] = val; si[tid] = idx;
    __syncthreads();
    for (int off = 128; off; off >>= 1) {
        if (tid < off) {
            float ov = sm[tid + off]; int oi = si[tid + off];
            if (ov > sm[tid] || (ov == sm[tid] && oi < si[tid])) { sm[tid] = ov; si[tid] = oi; }
        }
        __syncthreads();
    }
    if (!tid) { d_tmax[b][blockIdx.x] = sm[0]; d_tidx[b][blockIdx.x] = si[0]; }
}

// ---------------- fused q-gemm + scores + softmax + attention ----------------
// 256 threads: each owns ONE output d-pair (256 pairs = 512 dims), full K loop.
__global__ void __launch_bounds__(256) attn_fused(const float* __restrict__ bq) {
    int r = blockIdx.x, b = r & 31, tid = threadIdx.x;
    __shared__ u64 xs[512];
    __shared__ float qs[512];
    __shared__ float ws[64];
    const float* hBr = &d_hB[0][0][0] + (size_t)r * HID;
    for (int i = tid; i < 512; i += 256) xs[i] = dup2(hBr[i]);
    __syncthreads();
    {   // q = tanh(hB[r] @ WqT + bq): one pair per thread, K=512
        const u64* W2 = (const u64*)d_WqT;
        u64 acc = 0ull;
#pragma unroll 4
        for (int kk = 0; kk < 512; kk++)
            acc = ffma2(xs[kk], __ldg(W2 + (size_t)kk * 256 + tid), acc);
        acc = fadd2(acc, *(const u64*)(bq + 2 * tid));
        qs[2 * tid]     = tanhf(lo2(acc));
        qs[2 * tid + 1] = tanhf(hi2(acc));
    }
    __syncthreads();
    int warp = tid >> 5, lane = tid & 31;
    for (int s = warp; s < SPA; s += 8) {
        const float* kp = &d_keys[b][s][0];
        float a = 0.f;
        for (int k = lane; k < HID; k += 32) a += qs[k] * kp[k];
        for (int o = 16; o; o >>= 1) a += __shfl_xor_sync(0xffffffffu, a, o);
        if (!lane) ws[s] = a * (1.f / 7.f);
    }
    __syncthreads();
    if (warp == 0) {    // warp-parallel softmax over 49
        float v1 = (lane < SPA) ? ws[lane] : -FLT_MAX;
        float v2 = (lane + 32 < SPA) ? ws[lane + 32] : -FLT_MAX;
        float m = fmaxf(v1, v2);
        for (int o = 16; o; o >>= 1) m = fmaxf(m, __shfl_xor_sync(0xffffffffu, m, o));
        float e1 = (lane < SPA) ? expf(v1 - m) : 0.f;
        float e2 = (lane + 32 < SPA) ? expf(v2 - m) : 0.f;
        float ssum = e1 + e2;
        for (int o = 16; o; o >>= 1) ssum += __shfl_xor_sync(0xffffffffu, ssum, o);
        float inv = 1.f / ssum;
        if (lane < SPA) ws[lane] = e1 * inv;
        if (lane + 32 < SPA) ws[lane + 32] = e2 * inv;
    }
    __syncthreads();
    {   // attn[d] = sum_s w[s]*vals[b][s][d], 256 d-pairs
        const u64* V2 = (const u64*)d_vals;
        u64 a = 0ull;
#pragma unroll
        for (int s = 0; s < SPA; s++)
            a = ffma2(dup2(ws[s]), __ldg(V2 + (size_t)(b * SPA + s) * 256 + tid), a);
        ((u64*)d_ah)[(size_t)r * 512 + tid] = a;
    }
}

// ---------------- fused hatt-gemm + tanh + final argmax ----------------
// 256 threads: each owns ONE output d-pair (256 pairs = 512 dims), K=1024.
__global__ void __launch_bounds__(256) hatt_fused(const float* __restrict__ hattb) {
    int r = blockIdx.x, tid = threadIdx.x;
    __shared__ u64 xs[1024];
    if (r < BAT && tid == 0) {          // finalize argmax -> next token
        float mx = d_tmax[r][0]; int bi = d_tidx[r][0];
#pragma unroll
        for (int i = 1; i < NVT; i++) {
            float v = d_tmax[r][i];
            if (v > mx) { mx = v; bi = d_tidx[r][i]; }
        }
        d_best[r] = bi;
    }
    const float* ar = &d_ah[r][0];
    for (int i = tid; i < 1024; i += 256) xs[i] = dup2(ar[i]);
    __syncthreads();
    const u64* W2 = (const u64*)d_hattWT;
    u64 acc = 0ull;
#pragma unroll 4
    for (int kk = 0; kk < 1024; kk++)
        acc = ffma2(xs[kk], __ldg(W2 + (size_t)kk * 256 + tid), acc);
    acc = fadd2(acc, *(const u64*)(hattb + 2 * tid));
    ((u64*)d_hA)[(size_t)r * 256 + tid] = pack2(tanhf(lo2(acc)), tanhf(hi2(acc)));
}

// ---------------- keys / values precompute ----------------
__global__ void kv_kernel(const float* __restrict__ chan, const float* __restrict__ Wk,
                          const float* __restrict__ bk, const float* __restrict__ Wv,
                          const float* __restrict__ bv) {
    int b = blockIdx.x;
    int d0 = blockIdx.y * 64;
    __shared__ float ct[64][SPA];
    __shared__ float wk[SPA][SPA], wv[SPA][SPA];
    __shared__ float bks[SPA], bvs[SPA];
    int tid = threadIdx.x;
    for (int i = tid; i < 64 * SPA; i += 256) {
        int d = i / SPA, s = i % SPA;
        ct[d][s] = chan[((size_t)b * HID + d0 + d) * SPA + s];
    }
    for (int i = tid; i < SPA * SPA; i += 256) {
        wk[i / SPA][i % SPA] = Wk[i];
        wv[i / SPA][i % SPA] = Wv[i];
    }
    if (tid < SPA) { bks[tid] = bk[tid]; bvs[tid] = bv[tid]; }
    __syncthreads();
    for (int i = tid; i < SPA * 64; i += 256) {
        int d = i & 63, s = i >> 6;
        float ak = bks[s], av = bvs[s];
#pragma unroll
        for (int sp = 0; sp < SPA; sp++) {
            float cv = ct[d][sp];
            ak += cv * wk[s][sp];
            av += cv * wv[s][sp];
        }
        d_keys[b][s][d0 + d] = tanhf(ak);
        d_vals[b][s][d0 + d] = tanhf(av);
    }
}

__global__ void init_kernel(const float* __restrict__ pooled, const int* __restrict__ sosp) {
    int b = blockIdx.x;
    int j = blockIdx.y * 256 + threadIdx.x;
    float pv = pooled[b * HID + j];
    d_hA[0][b][j] = pv; d_hA[1][b][j] = pv;
    d_cst[0][b][j] = pv; d_cst[1][b][j] = pv;
    if (j == 0) d_best[b] = sosp[0];
}

// res[:,:,0] — identical across batch
__global__ void logits0_kernel(const float* __restrict__ embed, const int* __restrict__ sosp,
                               const float* __restrict__ projW, const float* __restrict__ projb) {
    int warp = threadIdx.x >> 5, lane = threadIdx.x & 31;
    int v = blockIdx.x * 8 + warp;
    if (v >= VOC) return;
    int sos = sosp[0];
    const float* e = embed + (size_t)sos * HID;
    const float* w = projW + (size_t)v * HID;
    float acc = 0.f;
    for (int k = lane; k < HID; k += 32) acc += e[k] * w[k];
    for (int o = 16; o; o >>= 1) acc += __shfl_xor_sync(0xffffffffu, acc, o);
    float s = acc + projb[v];
    d_logits[0][lane][v] = s;   // lane == b
}

// ---------------- final [T][B][V] -> [B][V][T] ----------------
__global__ void out_transpose(float* __restrict__ out) {
    int b = blockIdx.x;
    int v0 = blockIdx.y * 128;
    __shared__ float tl[TMAX][129];
    int tid = threadIdx.x;
    for (int i = tid; i < TMAX * 128; i += 256) {
        int t = i >> 7, vi = i & 127;
        int v = v0 + vi;
        tl[t][vi] = (v < VOC) ? d_logits[t][b][v] : 0.f;
    }
    __syncthreads();
    for (int i = tid; i < 128 * TMAX; i += 256) {
        int vi = i / TMAX, t = i % TMAX;
        int v = v0 + vi;
        if (v < VOC) out[((size_t)b * VOC + v) * TMAX + t] = tl[t][vi];
    }
}

// ---------------- host ----------------
extern "C" void kernel_launch(void* const* d_in, const int* in_sizes, int n_in,
                              void* d_out, int out_size) {
    const float* img    = (const float*)d_in[0];
    const float* pooled = (const float*)d_in[1];
    const float* embed  = (const float*)d_in[2];
    const float* Wq     = (const float*)d_in[3];
    const float* bq     = (const float*)d_in[4];
    const float* Wk     = (const float*)d_in[5];
    const float* bk     = (const float*)d_in[6];
    const float* Wv     = (const float*)d_in[7];
    const float* bv     = (const float*)d_in[8];
    const float* Wih    = (const float*)d_in[9];
    const float* Whh    = (const float*)d_in[10];
    const float* bih    = (const float*)d_in[11];
    const float* bhh    = (const float*)d_in[12];
    const float* projW  = (const float*)d_in[13];
    const float* projb  = (const float*)d_in[14];
    const float* hattW  = (const float*)d_in[15];
    const float* hattb  = (const float*)d_in[16];
    const int*   sosp   = (const int*)d_in[17];
    float* out = (float*)d_out;

    float *pWcT, *pWqT, *pHattWT, *pProjWT, *pHA, *pHB, *pP1, *pP2;
    int* pBest;
    cudaGetSymbolAddress((void**)&pWcT, d_WcT);
    cudaGetSymbolAddress((void**)&pWqT, d_WqT);
    cudaGetSymbolAddress((void**)&pHattWT, d_hattWT);
    cudaGetSymbolAddress((void**)&pProjWT, d_projWT);
    cudaGetSymbolAddress((void**)&pHA, d_hA);
    cudaGetSymbolAddress((void**)&pHB, d_hB);
    cudaGetSymbolAddress((void**)&pP1, d_P1);
    cudaGetSymbolAddress((void**)&pP2, d_P2);
    cudaGetSymbolAddress((void**)&pBest, d_best);

    dim3 tb(32, 8);
    // WcT[l][k<512][n] = Wih[l][n][k]; k>=512 -> Whh
    transpose_k<<<dim3(16, 64), tb>>>(Wih,              pWcT,                    2048, 512, G4);
    transpose_k<<<dim3(16, 64), tb>>>(Whh,              pWcT + (size_t)512 * G4, 2048, 512, G4);
    transpose_k<<<dim3(16, 64), tb>>>(Wih + 2048 * 512, pWcT + (size_t)KXH * G4, 2048, 512, G4);
    transpose_k<<<dim3(16, 64), tb>>>(Whh + 2048 * 512, pWcT + (size_t)KXH * G4 + (size_t)512 * G4, 2048, 512, G4);
    transpose_k<<<dim3(16, 16), tb>>>(Wq,    pWqT,    512, 512,  512);
    transpose_k<<<dim3(32, 16), tb>>>(hattW, pHattWT, 512, 1024, 512);
    transpose_k<<<dim3(16, 313), tb>>>(projW, pProjWT, VOC, 512, VLD);

    kv_kernel<<<dim3(32, 8), 256>>>(img, Wk, bk, Wv, bv);
    init_kernel<<<dim3(32, 2), 256>>>(pooled, sosp);
    logits0_kernel<<<1250, 256>>>(embed, sosp, projW, projb);

    const float* hA0 = pHA;
    const float* hA1 = pHA + (size_t)BAT * HID;
    const float* hB0 = pHB;
    const float* hB1 = pHB + (size_t)BAT * HID;

    for (int t = 0; t < TMAX - 1; t++) {
        // LSTM layer 0: A = [embed[best] | hA0]
        gemm2<64><<<dim3(8, 16), 128>>>(nullptr, hA0, embed, pBest, pWcT, 1024, pP1, 1024);
        lstm_act2<<<32, 256>>>(0, bih, bhh);
        // LSTM layer 1: A = [hB0 | hA1]
        gemm2<64><<<dim3(8, 16), 128>>>(hB0, hA1, nullptr, nullptr,
                                        pWcT + (size_t)KXH * G4, 1024, pP1, 1024);
        lstm_act2<<<32, 256>>>(1, bih, bhh);
        // projection (K=512): A = hB1
        gemm2<64><<<dim3(40, 8), 128>>>(hB1, nullptr, nullptr, nullptr,
                                        pProjWT, 5120, pP2, 5120);
        proj_combine2<<<dim3(20, 32), 256>>>(t + 1, projb);
        if (t < TMAX - 2) {
            attn_fused<<<64, 256>>>(bq);
            hatt_fused<<<64, 256>>>(hattb);
        }
    }

    out_transpose<<<dim3(32, 79), 256>>>(out);
    (void)in_sizes; (void)n_in; (void)out_size;
}

// round 5
// speedup vs baseline: 1.0704x; 1.0704x over previous
#include <cuda_runtime.h>
#include <math.h>
#include <stdint.h>
#include <float.h>

#define LNUM 2
#define HID 512
#define TMAX 20
#define VOC 10000
#define BAT 32
#define SPA 49
#define G4 2048
#define KXH 1024
#define VLD 10240
#define NB 128
#define NT 256

typedef unsigned long long u64;

__device__ __forceinline__ u64 fadd2(u64 a, u64 b) {
    u64 d; asm("add.rn.f32x2 %0, %1, %2;" : "=l"(d) : "l"(a), "l"(b)); return d;
}
__device__ __forceinline__ float lo2(u64 v) { return __uint_as_float((unsigned)v); }
__device__ __forceinline__ float hi2(u64 v) { return __uint_as_float((unsigned)(v >> 32)); }
__device__ __forceinline__ float sigm(float x) { return 1.f / (1.f + expf(-x)); }

// ---------------- static device scratch ----------------
__device__ float d_WcT[LNUM][KXH][G4];        // [l][k][n]
__device__ float d_WqT[HID][HID];             // [k][d]
__device__ float d_hattWT[KXH][HID];          // [k][j]
__device__ float d_projWT[HID][VLD];          // [k][v] padded (pad stays 0)
__device__ float d_keys[BAT][SPA][HID];
__device__ float d_vals[BAT][SPA][HID];
__device__ float d_hA[LNUM][BAT][HID];
__device__ float d_hB[LNUM][BAT][HID];
__device__ float d_cst[LNUM][BAT][HID];
__device__ float d_q[LNUM*BAT][HID];
__device__ float d_attn[LNUM*BAT][HID];
__device__ float d_P1[16][BAT][G4];           // LSTM partials (ksplit 16)
__device__ float d_P2[8][BAT][VLD];           // proj partials (ksplit 8)
__device__ float d_logits[TMAX][BAT][VOC];
__device__ float d_tmax[BAT][4];
__device__ int   d_tidx[BAT][4];
__device__ int   d_best[BAT];
__device__ unsigned g_count;
__device__ unsigned g_gen;

// ---------------- multi-job transposes ----------------
__global__ void transA(const float* __restrict__ Wih, const float* __restrict__ Whh) {
    // 4 jobs: (Wih l0), (Whh l0), (Wih l1), (Whh l1) -> d_WcT slices. R=2048, C=512.
    __shared__ float tile[32][33];
    int z = blockIdx.z;
    const float* in = (z & 1) ? Whh : Wih;
    if (z >= 2) in += 2048 * 512;
    float* out = &d_WcT[0][0][0] + (size_t)(z >= 2 ? KXH : 0) * G4 + (size_t)(z & 1 ? 512 : 0) * G4;
    int c0 = blockIdx.x * 32, r0 = blockIdx.y * 32;
    int x = threadIdx.x;
    for (int y = threadIdx.y; y < 32; y += 8) {
        int r = r0 + y, c = c0 + x;
        tile[y][x] = (r < 2048 && c < 512) ? in[(size_t)r * 512 + c] : 0.f;
    }
    __syncthreads();
    for (int y = threadIdx.y; y < 32; y += 8) {
        int c = c0 + y, r = r0 + x;
        if (c < 512 && r < 2048) out[(size_t)c * G4 + r] = tile[x][y];
    }
}

__global__ void transB(const float* __restrict__ Wq, const float* __restrict__ hattW,
                       const float* __restrict__ projW) {
    __shared__ float tile[32][33];
    int z = blockIdx.z;
    const float* in; float* out; int R, C, oLd;
    if (z == 0)      { in = Wq;    out = &d_WqT[0][0];    R = 512;  C = 512;  oLd = 512; }
    else if (z == 1) { in = hattW; out = &d_hattWT[0][0]; R = 512;  C = 1024; oLd = 512; }
    else             { in = projW; out = &d_projWT[0][0]; R = VOC;  C = 512;  oLd = VLD; }
    int c0 = blockIdx.x * 32, r0 = blockIdx.y * 32;
    if (c0 >= C || r0 >= R) return;
    int x = threadIdx.x;
    for (int y = threadIdx.y; y < 32; y += 8) {
        int r = r0 + y, c = c0 + x;
        tile[y][x] = (r < R && c < C) ? in[(size_t)r * C + c] : 0.f;
    }
    __syncthreads();
    for (int y = threadIdx.y; y < 32; y += 8) {
        int c = c0 + y, r = r0 + x;
        if (c < C && r < R) out[(size_t)c * oLd + r] = tile[x][y];
    }
}

// ---------------- keys / values precompute ----------------
__global__ void kv_kernel(const float* __restrict__ chan, const float* __restrict__ Wk,
                          const float* __restrict__ bk, const float* __restrict__ Wv,
                          const float* __restrict__ bv) {
    int b = blockIdx.x;
    int d0 = blockIdx.y * 64;
    __shared__ float ct[64][SPA];
    __shared__ float wk[SPA][SPA], wv[SPA][SPA];
    __shared__ float bks[SPA], bvs[SPA];
    int tid = threadIdx.x;
    for (int i = tid; i < 64 * SPA; i += 256) {
        int d = i / SPA, s = i % SPA;
        ct[d][s] = chan[((size_t)b * HID + d0 + d) * SPA + s];
    }
    for (int i = tid; i < SPA * SPA; i += 256) {
        wk[i / SPA][i % SPA] = Wk[i];
        wv[i / SPA][i % SPA] = Wv[i];
    }
    if (tid < SPA) { bks[tid] = bk[tid]; bvs[tid] = bv[tid]; }
    __syncthreads();
    for (int i = tid; i < SPA * 64; i += 256) {
        int d = i & 63, s = i >> 6;
        float ak = bks[s], av = bvs[s];
#pragma unroll
        for (int sp = 0; sp < SPA; sp++) {
            float cv = ct[d][sp];
            ak += cv * wk[s][sp];
            av += cv * wv[s][sp];
        }
        d_keys[b][s][d0 + d] = tanhf(ak);
        d_vals[b][s][d0 + d] = tanhf(av);
    }
}

// ---------------- res[:,:,0] (identical across batch) ----------------
__global__ void logits0_kernel(const float* __restrict__ embed, const int* __restrict__ sosp,
                               const float* __restrict__ projW, const float* __restrict__ projb) {
    int warp = threadIdx.x >> 5, lane = threadIdx.x & 31;
    int v = blockIdx.x * 8 + warp;
    if (v >= VOC) return;
    int sos = sosp[0];
    const float* e = embed + (size_t)sos * HID;
    const float* w = projW + (size_t)v * HID;
    float acc = 0.f;
    for (int k = lane; k < HID; k += 32) acc += e[k] * w[k];
    for (int o = 16; o; o >>= 1) acc += __shfl_xor_sync(0xffffffffu, acc, o);
    float s = acc + projb[v];
    d_logits[0][lane][v] = s;   // lane == b
}

// ---------------- init: state + barrier ----------------
__global__ void init_kernel(const float* __restrict__ pooled, const int* __restrict__ sosp) {
    int b = blockIdx.x, j = threadIdx.x;   // 32 x 512
    float pv = pooled[b * HID + j];
    d_hA[0][b][j] = pv; d_hA[1][b][j] = pv;
    d_cst[0][b][j] = pv; d_cst[1][b][j] = pv;
    if (j == 0) d_best[b] = sosp[0];
    if (b == 0 && j == 0) { g_count = 0; g_gen = 0; }
}

// ---------------- persistent decode loop ----------------
__device__ __forceinline__ void gsync(unsigned& gen) {
    __syncthreads();
    if (threadIdx.x == 0) {
        gen++;
        __threadfence();
        if (atomicAdd(&g_count, 1) == NB - 1) {
            g_count = 0;
            __threadfence();
            *(volatile unsigned*)&g_gen = gen;
        } else {
            while (*(volatile unsigned*)&g_gen < gen) {}
        }
        __threadfence();   // CCTL.IVALL: invalidate L1 so fresh data is visible
    }
    __syncthreads();
}

__global__ void __launch_bounds__(NT) decode_loop(
    const float* __restrict__ embed, const float* __restrict__ bih,
    const float* __restrict__ bhh, const float* __restrict__ projb,
    const float* __restrict__ bq, const float* __restrict__ hattb)
{
    unsigned gen = *(volatile unsigned*)&g_gen;   // replay-safe base
    int bid = blockIdx.x, tid = threadIdx.x;
    __shared__ float As[64][36];
    __shared__ float xs[1024];
    __shared__ float red[256];
    __shared__ int   ridx[256];
    __shared__ float wts[64];

    for (int t = 0; t < TMAX - 1; t++) {
        // ===== Phase A/C: LSTM gemm (layer l), 16 ksplit x 8 ntiles = 128 tiles =====
        for (int l = 0; l < 2; l++) {
            {
                int ks = bid >> 3, nt = bid & 7, k0 = ks * 64;
                if (l == 0) {
                    if (tid < 32) ridx[tid] = d_best[tid];
                    __syncthreads();
                }
                for (int i = tid; i < 2048; i += NT) {
                    int kk = i & 63, m = i >> 6, k = k0 + kk;
                    float v;
                    if (l == 0) v = (k < 512) ? embed[(size_t)ridx[m] * HID + k] : d_hA[0][m][k - 512];
                    else        v = (k < 512) ? d_hB[0][m][k] : d_hA[1][m][k - 512];
                    As[kk][m] = v;
                }
                __syncthreads();
                int n = nt * 256 + tid;
                const float* Bp = &d_WcT[l][k0][0] + n;
                float acc[32];
#pragma unroll
                for (int m = 0; m < 32; m++) acc[m] = 0.f;
#pragma unroll 4
                for (int kk = 0; kk < 64; kk++) {
                    float bv = __ldg(Bp + (size_t)kk * G4);
#pragma unroll
                    for (int m = 0; m < 32; m++) acc[m] += As[kk][m] * bv;
                }
                float* Pp = &d_P1[0][0][0] + (size_t)(ks * 32) * G4 + n;
#pragma unroll
                for (int m = 0; m < 32; m++) Pp[(size_t)m * G4] = acc[m];
            }
            gsync(gen);
            // ===== Phase B/D: LSTM activation (2 threads per output) =====
            {
                int gid = bid * NT + tid;
                int out = gid >> 1, half = gid & 1;
                int b = out >> 9, j = out & 511;
                float s0 = 0.f, s1 = 0.f, s2 = 0.f, s3 = 0.f;
                const float* P = &d_P1[0][0][0];
#pragma unroll
                for (int ks = 0; ks < 8; ks++) {
                    size_t base = (size_t)((half * 8 + ks) * 32 + b) * G4 + j;
                    s0 += P[base];
                    s1 += P[base + 512];
                    s2 += P[base + 1024];
                    s3 += P[base + 1536];
                }
                s0 += __shfl_xor_sync(0xffffffffu, s0, 1);
                s1 += __shfl_xor_sync(0xffffffffu, s1, 1);
                s2 += __shfl_xor_sync(0xffffffffu, s2, 1);
                s3 += __shfl_xor_sync(0xffffffffu, s3, 1);
                if (!half) {
                    s0 += bih[l * G4 + j]        + bhh[l * G4 + j];
                    s1 += bih[l * G4 + 512 + j]  + bhh[l * G4 + 512 + j];
                    s2 += bih[l * G4 + 1024 + j] + bhh[l * G4 + 1024 + j];
                    s3 += bih[l * G4 + 1536 + j] + bhh[l * G4 + 1536 + j];
                    float i_ = sigm(s0), f_ = sigm(s1), gg = tanhf(s2), o_ = sigm(s3);
                    float c2 = f_ * d_cst[l][b][j] + i_ * gg;
                    float h2 = o_ * tanhf(c2);
                    d_cst[l][b][j] = c2;
                    d_hB[l][b][j] = h2;
                }
            }
            gsync(gen);
        }
        // ===== Phase E: proj gemm, 40 ntiles x 8 ksplit = 320 tiles, 3 rounds =====
        for (int r = 0; r < 3; r++) {
            int tile = bid + NB * r;
            if (tile < 320) {
                int nt = tile % 40, ks = tile / 40, k0 = ks * 64;
                __syncthreads();
                for (int i = tid; i < 2048; i += NT) {
                    int kk = i & 63, m = i >> 6;
                    As[kk][m] = d_hB[1][m][k0 + kk];
                }
                __syncthreads();
                int n = nt * 256 + tid;
                const float* Bp = &d_projWT[k0][0] + n;
                float acc[32];
#pragma unroll
                for (int m = 0; m < 32; m++) acc[m] = 0.f;
#pragma unroll 4
                for (int kk = 0; kk < 64; kk++) {
                    float bv = __ldg(Bp + (size_t)kk * VLD);
#pragma unroll
                    for (int m = 0; m < 32; m++) acc[m] += As[kk][m] * bv;
                }
                float* Pp = &d_P2[0][0][0] + (size_t)(ks * 32) * VLD + n;
#pragma unroll
                for (int m = 0; m < 32; m++) Pp[(size_t)m * VLD] = acc[m];
            }
        }
        gsync(gen);
        // ===== Phase F: combine partials -> logits[t+1] + per-quarter argmax =====
        {
            int b = bid >> 2, q = bid & 3;
            const u64* P2u = (const u64*)&d_P2[0][0][0];
            const u64* pb2 = (const u64*)projb;
            float best = -FLT_MAX; int bidx = 0x7fffffff;
#pragma unroll
            for (int i = 0; i < 5; i++) {
                int vp = q * 1280 + i * 256 + tid;
                u64 s = 0ull;
#pragma unroll
                for (int ks = 0; ks < 8; ks++)
                    s = fadd2(s, P2u[(size_t)(ks * 32 + b) * 5120 + vp]);
                if (vp < 5000) {
                    s = fadd2(s, pb2[vp]);
                    ((u64*)&d_logits[0][0][0])[((size_t)(t + 1) * 32 + b) * 5000 + vp] = s;
                    float lo = lo2(s), hi = hi2(s);
                    if (lo > best) { best = lo; bidx = 2 * vp; }
                    if (hi > best) { best = hi; bidx = 2 * vp + 1; }
                }
            }
            red[tid] = best; ridx[tid] = bidx;
            __syncthreads();
            for (int off = 128; off; off >>= 1) {
                if (tid < off) {
                    float ov = red[tid + off]; int oi = ridx[tid + off];
                    if (ov > red[tid] || (ov == red[tid] && oi < ridx[tid])) {
                        red[tid] = ov; ridx[tid] = oi;
                    }
                }
                __syncthreads();
            }
            if (!tid) { d_tmax[b][q] = red[0]; d_tidx[b][q] = ridx[0]; }
        }
        gsync(gen);

        if (t < TMAX - 2) {
            // ===== Phase G: final argmax (blocks 0-31) || q-gemm (blocks 32-95) =====
            if (bid < 32) {
                if (tid == 0) {
                    float mx = d_tmax[bid][0]; int bi = d_tidx[bid][0];
#pragma unroll
                    for (int q = 1; q < 4; q++) {
                        float v = d_tmax[bid][q];
                        if (v > mx) { mx = v; bi = d_tidx[bid][q]; }
                    }
                    d_best[bid] = bi;
                }
            } else if (bid < 96) {
                int r = bid - 32;
                const float* hBr = &d_hB[0][0][0] + (size_t)r * HID;
                for (int i = tid; i < 512; i += NT) xs[i] = hBr[i];
                __syncthreads();
                const float2* W2 = (const float2*)&d_WqT[0][0];
                float ax = 0.f, ay = 0.f;
#pragma unroll 4
                for (int k = 0; k < 512; k++) {
                    float xv = xs[k];
                    float2 w = __ldg(W2 + (size_t)k * 256 + tid);
                    ax += xv * w.x; ay += xv * w.y;
                }
                float2 bb = ((const float2*)bq)[tid];
                float2 qv; qv.x = tanhf(ax + bb.x); qv.y = tanhf(ay + bb.y);
                ((float2*)&d_q[0][0])[(size_t)r * 256 + tid] = qv;
            }
            gsync(gen);
            // ===== Phase H: attention (blocks 0-63) =====
            if (bid < 64) {
                int r = bid, b = r & 31;
                const float* qr = &d_q[r][0];
                for (int i = tid; i < 512; i += NT) xs[i] = qr[i];
                __syncthreads();
                int warp = tid >> 5, lane = tid & 31;
                for (int s = warp; s < SPA; s += 8) {
                    const float* kp = &d_keys[b][s][0];
                    float a = 0.f;
                    for (int k = lane; k < HID; k += 32) a += xs[k] * kp[k];
                    for (int o = 16; o; o >>= 1) a += __shfl_xor_sync(0xffffffffu, a, o);
                    if (!lane) wts[s] = a * (1.f / 7.f);
                }
                __syncthreads();
                if (warp == 0) {
                    float v1 = (lane < SPA) ? wts[lane] : -FLT_MAX;
                    float v2 = (lane + 32 < SPA) ? wts[lane + 32] : -FLT_MAX;
                    float m = fmaxf(v1, v2);
                    for (int o = 16; o; o >>= 1) m = fmaxf(m, __shfl_xor_sync(0xffffffffu, m, o));
                    float e1 = (lane < SPA) ? expf(v1 - m) : 0.f;
                    float e2 = (lane + 32 < SPA) ? expf(v2 - m) : 0.f;
                    float ssum = e1 + e2;
                    for (int o = 16; o; o >>= 1) ssum += __shfl_xor_sync(0xffffffffu, ssum, o);
                    float inv = 1.f / ssum;
                    if (lane < SPA) wts[lane] = e1 * inv;
                    if (lane + 32 < SPA) wts[lane + 32] = e2 * inv;
                }
                __syncthreads();
                const float2* V2 = (const float2*)&d_vals[0][0][0];
                float ax = 0.f, ay = 0.f;
#pragma unroll
                for (int s = 0; s < SPA; s++) {
                    float w = wts[s];
                    float2 v = __ldg(V2 + (size_t)(b * SPA + s) * 256 + tid);
                    ax += w * v.x; ay += w * v.y;
                }
                float2 av; av.x = ax; av.y = ay;
                ((float2*)&d_attn[0][0])[(size_t)r * 256 + tid] = av;
            }
            gsync(gen);
            // ===== Phase I: hatt gemm + tanh -> hA (blocks 0-63) =====
            if (bid < 64) {
                int r = bid;
                const float* ar = &d_attn[r][0];
                const float* hBr = &d_hB[0][0][0] + (size_t)r * HID;
                for (int i = tid; i < 512; i += NT) { xs[i] = ar[i]; xs[512 + i] = hBr[i]; }
                __syncthreads();
                const float2* W2 = (const float2*)&d_hattWT[0][0];
                float ax = 0.f, ay = 0.f;
#pragma unroll 4
                for (int k = 0; k < 1024; k++) {
                    float xv = xs[k];
                    float2 w = __ldg(W2 + (size_t)k * 256 + tid);
                    ax += xv * w.x; ay += xv * w.y;
                }
                float2 bb = ((const float2*)hattb)[tid];
                float2 hv; hv.x = tanhf(ax + bb.x); hv.y = tanhf(ay + bb.y);
                ((float2*)&d_hA[0][0][0])[(size_t)r * 256 + tid] = hv;
            }
            gsync(gen);
        }
    }
}

// ---------------- final [T][B][V] -> [B][V][T] ----------------
__global__ void out_transpose(float* __restrict__ out) {
    int b = blockIdx.x;
    int v0 = blockIdx.y * 128;
    __shared__ float tl[TMAX][129];
    int tid = threadIdx.x;
    for (int i = tid; i < TMAX * 128; i += 256) {
        int t = i >> 7, vi = i & 127;
        int v = v0 + vi;
        tl[t][vi] = (v < VOC) ? d_logits[t][b][v] : 0.f;
    }
    __syncthreads();
    for (int i = tid; i < 128 * TMAX; i += 256) {
        int vi = i / TMAX, t = i % TMAX;
        int v = v0 + vi;
        if (v < VOC) out[((size_t)b * VOC + v) * TMAX + t] = tl[t][vi];
    }
}

// ---------------- host ----------------
extern "C" void kernel_launch(void* const* d_in, const int* in_sizes, int n_in,
                              void* d_out, int out_size) {
    const float* img    = (const float*)d_in[0];
    const float* pooled = (const float*)d_in[1];
    const float* embed  = (const float*)d_in[2];
    const float* Wq     = (const float*)d_in[3];
    const float* bq     = (const float*)d_in[4];
    const float* Wk     = (const float*)d_in[5];
    const float* bk     = (const float*)d_in[6];
    const float* Wv     = (const float*)d_in[7];
    const float* bv     = (const float*)d_in[8];
    const float* Wih    = (const float*)d_in[9];
    const float* Whh    = (const float*)d_in[10];
    const float* bih    = (const float*)d_in[11];
    const float* bhh    = (const float*)d_in[12];
    const float* projW  = (const float*)d_in[13];
    const float* projb  = (const float*)d_in[14];
    const float* hattW  = (const float*)d_in[15];
    const float* hattb  = (const float*)d_in[16];
    const int*   sosp   = (const int*)d_in[17];
    float* out = (float*)d_out;

    dim3 tb(32, 8);
    transA<<<dim3(16, 64, 4), tb>>>(Wih, Whh);                  // node 0
    transB<<<dim3(32, 313, 3), tb>>>(Wq, hattW, projW);         // node 1
    kv_kernel<<<dim3(32, 8), 256>>>(img, Wk, bk, Wv, bv);       // node 2
    logits0_kernel<<<1250, 256>>>(embed, sosp, projW, projb);   // node 3
    init_kernel<<<32, 512>>>(pooled, sosp);                     // node 4
    decode_loop<<<NB, NT>>>(embed, bih, bhh, projb, bq, hattb); // node 5 (ncu target)
    out_transpose<<<dim3(32, 79), 256>>>(out);                  // node 6
    (void)in_sizes; (void)n_in; (void)out_size;
}

// round 6
// speedup vs baseline: 2.0803x; 1.9435x over previous
#include <cuda_runtime.h>
#include <math.h>
#include <stdint.h>
#include <float.h>

#define LNUM 2
#define HID 512
#define TMAX 20
#define VOC 10000
#define BAT 32
#define SPA 49
#define G4 2048
#define KXH 1024
#define VLD 10240
#define NB 256
#define NT 256

typedef unsigned long long u64;

__device__ __forceinline__ u64 ffma2(u64 a, u64 b, u64 c) {
    u64 d; asm("fma.rn.f32x2 %0, %1, %2, %3;" : "=l"(d) : "l"(a), "l"(b), "l"(c)); return d;
}
__device__ __forceinline__ u64 fadd2(u64 a, u64 b) {
    u64 d; asm("add.rn.f32x2 %0, %1, %2;" : "=l"(d) : "l"(a), "l"(b)); return d;
}
__device__ __forceinline__ u64 dup2(float x) {
    u64 d; unsigned u = __float_as_uint(x);
    asm("mov.b64 %0, {%1, %2};" : "=l"(d) : "r"(u), "r"(u)); return d;
}
__device__ __forceinline__ u64 pack2(float x, float y) {
    u64 d; unsigned a = __float_as_uint(x), b = __float_as_uint(y);
    asm("mov.b64 %0, {%1, %2};" : "=l"(d) : "r"(a), "r"(b)); return d;
}
__device__ __forceinline__ float lo2(u64 v) { return __uint_as_float((unsigned)v); }
__device__ __forceinline__ float hi2(u64 v) { return __uint_as_float((unsigned)(v >> 32)); }
__device__ __forceinline__ float sigm(float x) { return 1.f / (1.f + expf(-x)); }

// ---------------- static device scratch ----------------
__device__ float d_WcT[LNUM][KXH][G4];        // [l][k][n]
__device__ float d_WqT[HID][HID];             // [k][d]
__device__ float d_hattWT[KXH][HID];          // [k][j]
__device__ float d_projWT[HID][VLD];          // [k][v] padded (pad stays 0)
__device__ float d_keys[BAT][SPA][HID];
__device__ float d_vals[BAT][SPA][HID];
__device__ float d_hA[LNUM][BAT][HID];
__device__ float d_hB[LNUM][BAT][HID];
__device__ float d_cst[LNUM][BAT][HID];
__device__ float d_q[LNUM*BAT][HID];
__device__ float d_attn[LNUM*BAT][HID];
__device__ float d_P1[32][BAT][G4];           // LSTM partials (ksplit 32)
__device__ float d_P2[8][BAT][VLD];           // proj partials (ksplit 8)
__device__ float d_Pq[8][LNUM*BAT][HID];      // q partials
__device__ float d_Ph[32][LNUM*BAT][HID];     // hatt partials
__device__ float d_logits[TMAX][BAT][VOC];
__device__ u64   d_bestKey[BAT];
__device__ int   d_best[BAT];
__device__ unsigned g_count;
__device__ unsigned g_gen;

// ---------------- multi-job transposes ----------------
__global__ void transA(const float* __restrict__ Wih, const float* __restrict__ Whh) {
    __shared__ float tile[32][33];
    int z = blockIdx.z;
    const float* in = (z & 1) ? Whh : Wih;
    if (z >= 2) in += 2048 * 512;
    float* out = &d_WcT[0][0][0] + (size_t)(z >= 2 ? KXH : 0) * G4 + (size_t)(z & 1 ? 512 : 0) * G4;
    int c0 = blockIdx.x * 32, r0 = blockIdx.y * 32;
    int x = threadIdx.x;
    for (int y = threadIdx.y; y < 32; y += 8) {
        int r = r0 + y, c = c0 + x;
        tile[y][x] = (r < 2048 && c < 512) ? in[(size_t)r * 512 + c] : 0.f;
    }
    __syncthreads();
    for (int y = threadIdx.y; y < 32; y += 8) {
        int c = c0 + y, r = r0 + x;
        if (c < 512 && r < 2048) out[(size_t)c * G4 + r] = tile[x][y];
    }
}

__global__ void transB(const float* __restrict__ Wq, const float* __restrict__ hattW,
                       const float* __restrict__ projW) {
    __shared__ float tile[32][33];
    int z = blockIdx.z;
    const float* in; float* out; int R, C, oLd;
    if (z == 0)      { in = Wq;    out = &d_WqT[0][0];    R = 512;  C = 512;  oLd = 512; }
    else if (z == 1) { in = hattW; out = &d_hattWT[0][0]; R = 512;  C = 1024; oLd = 512; }
    else             { in = projW; out = &d_projWT[0][0]; R = VOC;  C = 512;  oLd = VLD; }
    int c0 = blockIdx.x * 32, r0 = blockIdx.y * 32;
    if (c0 >= C || r0 >= R) return;
    int x = threadIdx.x;
    for (int y = threadIdx.y; y < 32; y += 8) {
        int r = r0 + y, c = c0 + x;
        tile[y][x] = (r < R && c < C) ? in[(size_t)r * C + c] : 0.f;
    }
    __syncthreads();
    for (int y = threadIdx.y; y < 32; y += 8) {
        int c = c0 + y, r = r0 + x;
        if (c < C && r < R) out[(size_t)c * oLd + r] = tile[x][y];
    }
}

// ---------------- keys / values precompute + state init ----------------
__global__ void kvinit_kernel(const float* __restrict__ chan, const float* __restrict__ Wk,
                              const float* __restrict__ bk, const float* __restrict__ Wv,
                              const float* __restrict__ bv, const float* __restrict__ pooled,
                              const int* __restrict__ sosp) {
    int b = blockIdx.x;
    int d0 = blockIdx.y * 64;
    __shared__ float ct[64][SPA];
    __shared__ float wk[SPA][SPA], wv[SPA][SPA];
    __shared__ float bks[SPA], bvs[SPA];
    int tid = threadIdx.x;
    if (blockIdx.y == 0) {   // init work
        for (int j = tid; j < HID; j += 256) {
            float pv = pooled[b * HID + j];
            d_hA[0][b][j] = pv; d_hA[1][b][j] = pv;
            d_cst[0][b][j] = pv; d_cst[1][b][j] = pv;
        }
        if (tid == 0) {
            d_best[b] = sosp[0];
            d_bestKey[b] = 0ull;
            if (b == 0) { g_count = 0; g_gen = 0; }
        }
    }
    for (int i = tid; i < 64 * SPA; i += 256) {
        int d = i / SPA, s = i % SPA;
        ct[d][s] = chan[((size_t)b * HID + d0 + d) * SPA + s];
    }
    for (int i = tid; i < SPA * SPA; i += 256) {
        wk[i / SPA][i % SPA] = Wk[i];
        wv[i / SPA][i % SPA] = Wv[i];
    }
    if (tid < SPA) { bks[tid] = bk[tid]; bvs[tid] = bv[tid]; }
    __syncthreads();
    for (int i = tid; i < SPA * 64; i += 256) {
        int d = i & 63, s = i >> 6;
        float ak = bks[s], av = bvs[s];
#pragma unroll
        for (int sp = 0; sp < SPA; sp++) {
            float cv = ct[d][sp];
            ak += cv * wk[s][sp];
            av += cv * wv[s][sp];
        }
        d_keys[b][s][d0 + d] = tanhf(ak);
        d_vals[b][s][d0 + d] = tanhf(av);
    }
}

// ---------------- res[:,:,0] (identical across batch) ----------------
__global__ void logits0_kernel(const float* __restrict__ embed, const int* __restrict__ sosp,
                               const float* __restrict__ projW, const float* __restrict__ projb) {
    int warp = threadIdx.x >> 5, lane = threadIdx.x & 31;
    int v = blockIdx.x * 8 + warp;
    if (v >= VOC) return;
    int sos = sosp[0];
    const float* e = embed + (size_t)sos * HID;
    const float* w = projW + (size_t)v * HID;
    float acc = 0.f;
    for (int k = lane; k < HID; k += 32) acc += e[k] * w[k];
    for (int o = 16; o; o >>= 1) acc += __shfl_xor_sync(0xffffffffu, acc, o);
    float s = acc + projb[v];
    d_logits[0][lane][v] = s;   // lane == b
}

// ---------------- persistent decode ----------------
__device__ __forceinline__ void gsync(unsigned& gen) {
    __syncthreads();
    if (threadIdx.x == 0) {
        gen++;
        __threadfence();
        if (atomicAdd(&g_count, 1) == NB - 1) {
            g_count = 0;
            __threadfence();
            *(volatile unsigned*)&g_gen = gen;
        } else {
            while (*(volatile unsigned*)&g_gen < gen) {}
        }
        __threadfence();
    }
    __syncthreads();
}

__global__ void __launch_bounds__(NT, 2) decode_loop(
    const float* __restrict__ embed, const float* __restrict__ bih,
    const float* __restrict__ bhh, const float* __restrict__ projb,
    const float* __restrict__ bq, const float* __restrict__ hattb)
{
    unsigned gen = *(volatile unsigned*)&g_gen;
    int bid = blockIdx.x, tid = threadIdx.x;
    __shared__ __align__(16) char shraw[64 * 33 * 8];   // 16.9KB union
    __shared__ int sbest[32];
    float (*As)[33]  = (float(*)[33])shraw;             // [32][33] scalar LSTM stage
    u64   (*As2)[33] = (u64(*)[33])shraw;               // [64][33] f32x2 stage
    float* xs  = (float*)shraw;                          // attn q
    float* wts = (float*)(shraw + 2048);                 // attn weights
    float* red = (float*)shraw;                          // F' reduce
    int*   ridx = (int*)(shraw + 1024);

    const float* hA0 = &d_hA[0][0][0];
    const float* hA1 = &d_hA[1][0][0];
    const float* hB0 = &d_hB[0][0][0];
    const float* hB1 = &d_hB[1][0][0];
    const float* hBf = &d_hB[0][0][0];

    for (int t = 0; t < TMAX - 1; t++) {
        // ===== A / C: LSTM gemm (scalar, KC=32, 32ks x 8nt = 256 tiles) =====
        for (int l = 0; l < 2; l++) {
            {
                int ks = bid >> 3, nt = bid & 7, k0 = ks * 32;
                if (l == 0) {
                    if (tid < 32) sbest[tid] = d_best[tid];
                }
                __syncthreads();
                for (int i = tid; i < 1024; i += NT) {
                    int kk = i & 31, m = i >> 5, k = k0 + kk;
                    float v;
                    if (l == 0) v = (k < 512) ? embed[(size_t)sbest[m] * HID + k] : hA0[m * HID + (k - 512)];
                    else        v = (k < 512) ? hB0[m * HID + k] : hA1[m * HID + (k - 512)];
                    As[kk][m] = v;
                }
                __syncthreads();
                int n = nt * 256 + tid;
                const float* Bp = &d_WcT[l][k0][0] + n;
                float acc[32];
#pragma unroll
                for (int m = 0; m < 32; m++) acc[m] = 0.f;
#pragma unroll 4
                for (int kk = 0; kk < 32; kk++) {
                    float bv = __ldg(Bp); Bp += G4;
#pragma unroll
                    for (int m = 0; m < 32; m++) acc[m] += As[kk][m] * bv;
                }
                float* Pp = &d_P1[0][0][0] + (size_t)(ks * 32) * G4 + n;
#pragma unroll
                for (int m = 0; m < 32; m++) Pp[(size_t)m * G4] = acc[m];
            }
            gsync(gen);
            // ===== B / D: activation (64 blocks, 1 thread per output) =====
            if (bid < 64) {
                int out = bid * 256 + tid;
                int b = out >> 9, j = out & 511;
                float s0 = bih[l * G4 + j]        + bhh[l * G4 + j];
                float s1 = bih[l * G4 + 512 + j]  + bhh[l * G4 + 512 + j];
                float s2 = bih[l * G4 + 1024 + j] + bhh[l * G4 + 1024 + j];
                float s3 = bih[l * G4 + 1536 + j] + bhh[l * G4 + 1536 + j];
                const float* P = &d_P1[0][0][0];
#pragma unroll 8
                for (int ks = 0; ks < 32; ks++) {
                    size_t base = (size_t)(ks * 32 + b) * G4 + j;
                    s0 += P[base];
                    s1 += P[base + 512];
                    s2 += P[base + 1024];
                    s3 += P[base + 1536];
                }
                float i_ = sigm(s0), f_ = sigm(s1), gg = tanhf(s2), o_ = sigm(s3);
                float c2 = f_ * d_cst[l][b][j] + i_ * gg;
                float h2 = o_ * tanhf(c2);
                d_cst[l][b][j] = c2;
                d_hB[l][b][j] = h2;
            }
            gsync(gen);
        }
        // ===== E': proj gemm (f32x2, 8ks x 20nt = 160 blks) || q gemm (16 blks) =====
        if (bid < 160) {
            int nt = bid % 20, ks = bid / 20, k0 = ks * 64;
            __syncthreads();
            for (int i = tid; i < 2048; i += NT) {
                int kk = i & 63, m = i >> 6;
                As2[kk][m] = dup2(hB1[m * HID + k0 + kk]);
            }
            __syncthreads();
            int np = nt * 256 + tid;
            const u64* Bp = (const u64*)&d_projWT[k0][0] + np;
            u64 acc[32];
#pragma unroll
            for (int m = 0; m < 32; m++) acc[m] = 0ull;
#pragma unroll 4
            for (int kk = 0; kk < 64; kk++) {
                u64 bv = __ldg(Bp); Bp += VLD / 2;
#pragma unroll
                for (int m = 0; m < 32; m++) acc[m] = ffma2(As2[kk][m], bv, acc[m]);
            }
            u64* Pp = (u64*)&d_P2[0][0][0] + (size_t)(ks * 32) * (VLD / 2) + np;
#pragma unroll
            for (int m = 0; m < 32; m++) Pp[(size_t)m * (VLD / 2)] = acc[m];
        } else if (bid < 176) {
            int idx = bid - 160, l = idx & 1, ks = idx >> 1, k0 = ks * 64;
            __syncthreads();
            for (int i = tid; i < 2048; i += NT) {
                int kk = i & 63, m = i >> 6;
                As2[kk][m] = dup2(d_hB[l][m][k0 + kk]);
            }
            __syncthreads();
            const u64* Bp = (const u64*)&d_WqT[k0][0] + tid;
            u64 acc[32];
#pragma unroll
            for (int m = 0; m < 32; m++) acc[m] = 0ull;
#pragma unroll 4
            for (int kk = 0; kk < 64; kk++) {
                u64 bv = __ldg(Bp); Bp += 256;
#pragma unroll
                for (int m = 0; m < 32; m++) acc[m] = ffma2(As2[kk][m], bv, acc[m]);
            }
            u64* Pp = (u64*)&d_Pq[0][0][0] + (size_t)(ks * 64 + l * 32) * 256 + tid;
#pragma unroll
            for (int m = 0; m < 32; m++) Pp[(size_t)m * 256] = acc[m];
        } else if (bid == 176) {
            __syncthreads();
            if (tid < 32) d_bestKey[tid] = 0ull;   // reset for this step's atomicMax
        } else { __syncthreads(); }
        gsync(gen);
        // ===== F': proj combine + logits + argmax (128 blks) || q combine+tanh (16) =====
        if (bid < 128) {
            int b = bid >> 2, q = bid & 3;
            const u64* P2u = (const u64*)&d_P2[0][0][0];
            const u64* pb2 = (const u64*)projb;
            float best = -FLT_MAX; int bidx = 0x7fffffff;
            __syncthreads();
#pragma unroll
            for (int i = 0; i < 5; i++) {
                int vp = q * 1280 + i * 256 + tid;
                u64 s = 0ull;
#pragma unroll
                for (int ks = 0; ks < 8; ks++)
                    s = fadd2(s, P2u[(size_t)(ks * 32 + b) * 5120 + vp]);
                if (vp < 5000) {
                    s = fadd2(s, pb2[vp]);
                    ((u64*)&d_logits[0][0][0])[((size_t)(t + 1) * 32 + b) * 5000 + vp] = s;
                    float lo = lo2(s), hi = hi2(s);
                    if (lo > best) { best = lo; bidx = 2 * vp; }
                    if (hi > best) { best = hi; bidx = 2 * vp + 1; }
                }
            }
            red[tid] = best; ridx[tid] = bidx;
            __syncthreads();
            for (int off = 128; off; off >>= 1) {
                if (tid < off) {
                    float ov = red[tid + off]; int oi = ridx[tid + off];
                    if (ov > red[tid] || (ov == red[tid] && oi < ridx[tid])) {
                        red[tid] = ov; ridx[tid] = oi;
                    }
                }
                __syncthreads();
            }
            if (!tid) {
                unsigned u = __float_as_uint(red[0]);
                unsigned mk = u ^ (unsigned)(((int)u >> 31) | 0x80000000);
                u64 key = ((u64)mk << 32) | (u64)(0xFFFFFFFFu - (unsigned)ridx[0]);
                atomicMax(&d_bestKey[b], key);
            }
        } else if (bid < 144) {
            __syncthreads();
            int gid = (bid - 128) * 256 + tid;
            const u64* Pq2 = (const u64*)&d_Pq[0][0][0];
            const u64* bq2 = (const u64*)bq;
#pragma unroll
            for (int rep = 0; rep < 4; rep++) {
                int p = rep * 4096 + gid;
                int r = p >> 8, pr = p & 255;
                u64 s = 0ull;
#pragma unroll
                for (int ks = 0; ks < 8; ks++)
                    s = fadd2(s, Pq2[(size_t)(ks * 64 + r) * 256 + pr]);
                s = fadd2(s, bq2[pr]);
                ((u64*)&d_q[0][0])[(size_t)r * 256 + pr] = pack2(tanhf(lo2(s)), tanhf(hi2(s)));
            }
        } else { __syncthreads(); }
        gsync(gen);

        if (t < TMAX - 2) {
            // ===== G': attention (64 blks) + best decode (32 of them) =====
            if (bid < 64) {
                int r = bid, b = r & 31;
                if (r < 32 && tid == 0) {
                    unsigned low = (unsigned)(d_bestKey[r] & 0xFFFFFFFFull);
                    d_best[r] = (int)(0xFFFFFFFFu - low);
                }
                __syncthreads();
                const float* qr = &d_q[r][0];
                for (int i = tid; i < 512; i += NT) xs[i] = qr[i];
                __syncthreads();
                int warp = tid >> 5, lane = tid & 31;
                for (int s = warp; s < SPA; s += 8) {
                    const float* kp = &d_keys[b][s][0];
                    float a = 0.f;
                    for (int k = lane; k < HID; k += 32) a += xs[k] * kp[k];
                    for (int o = 16; o; o >>= 1) a += __shfl_xor_sync(0xffffffffu, a, o);
                    if (!lane) wts[s] = a * (1.f / 7.f);
                }
                __syncthreads();
                if (warp == 0) {
                    float v1 = (lane < SPA) ? wts[lane] : -FLT_MAX;
                    float v2 = (lane + 32 < SPA) ? wts[lane + 32] : -FLT_MAX;
                    float m = fmaxf(v1, v2);
                    for (int o = 16; o; o >>= 1) m = fmaxf(m, __shfl_xor_sync(0xffffffffu, m, o));
                    float e1 = (lane < SPA) ? expf(v1 - m) : 0.f;
                    float e2 = (lane + 32 < SPA) ? expf(v2 - m) : 0.f;
                    float ssum = e1 + e2;
                    for (int o = 16; o; o >>= 1) ssum += __shfl_xor_sync(0xffffffffu, ssum, o);
                    float inv = 1.f / ssum;
                    if (lane < SPA) wts[lane] = e1 * inv;
                    if (lane + 32 < SPA) wts[lane + 32] = e2 * inv;
                }
                __syncthreads();
                const u64* V2 = (const u64*)&d_vals[0][0][0];
                u64 a = 0ull;
#pragma unroll
                for (int s = 0; s < SPA; s++)
                    a = ffma2(dup2(wts[s]), __ldg(V2 + (size_t)(b * SPA + s) * 256 + tid), a);
                ((u64*)&d_attn[0][0])[(size_t)r * 256 + tid] = a;
            } else { __syncthreads(); __syncthreads(); __syncthreads(); __syncthreads(); }
            gsync(gen);
            // ===== H': hatt gemm (f32x2, 32ks x 2 ltiles = 64 blks, KC=32) =====
            if (bid < 64) {
                int l = bid & 1, ks = bid >> 1, k0 = ks * 32;
                __syncthreads();
                for (int i = tid; i < 1024; i += NT) {
                    int kk = i & 31, m = i >> 5, k = k0 + kk;
                    int r = l * 32 + m;
                    float v = (k < 512) ? d_attn[r][k] : hBf[r * HID + (k - 512)];
                    As2[kk][m] = dup2(v);
                }
                __syncthreads();
                const u64* Bp = (const u64*)&d_hattWT[k0][0] + tid;
                u64 acc[32];
#pragma unroll
                for (int m = 0; m < 32; m++) acc[m] = 0ull;
#pragma unroll 4
                for (int kk = 0; kk < 32; kk++) {
                    u64 bv = __ldg(Bp); Bp += 256;
#pragma unroll
                    for (int m = 0; m < 32; m++) acc[m] = ffma2(As2[kk][m], bv, acc[m]);
                }
                u64* Pp = (u64*)&d_Ph[0][0][0] + (size_t)(ks * 64 + l * 32) * 256 + tid;
#pragma unroll
                for (int m = 0; m < 32; m++) Pp[(size_t)m * 256] = acc[m];
            } else { __syncthreads(); __syncthreads(); }
            gsync(gen);
            // ===== I': hatt combine + tanh -> hA (64 blks) =====
            if (bid < 64) {
                int r = bid;
                const u64* Ph2 = (const u64*)&d_Ph[0][0][0];
                u64 s = 0ull;
#pragma unroll
                for (int ks = 0; ks < 32; ks++)
                    s = fadd2(s, Ph2[(size_t)(ks * 64 + r) * 256 + tid]);
                s = fadd2(s, ((const u64*)hattb)[tid]);
                ((u64*)&d_hA[0][0][0])[(size_t)r * 256 + tid] = pack2(tanhf(lo2(s)), tanhf(hi2(s)));
            }
            gsync(gen);
        }
    }
}

// ---------------- final [T][B][V] -> [B][V][T] ----------------
__global__ void out_transpose(float* __restrict__ out) {
    int b = blockIdx.x;
    int v0 = blockIdx.y * 128;
    __shared__ float tl[TMAX][129];
    int tid = threadIdx.x;
    for (int i = tid; i < TMAX * 128; i += 256) {
        int t = i >> 7, vi = i & 127;
        int v = v0 + vi;
        tl[t][vi] = (v < VOC) ? d_logits[t][b][v] : 0.f;
    }
    __syncthreads();
    for (int i = tid; i < 128 * TMAX; i += 256) {
        int vi = i / TMAX, t = i % TMAX;
        int v = v0 + vi;
        if (v < VOC) out[((size_t)b * VOC + v) * TMAX + t] = tl[t][vi];
    }
}

// ---------------- host ----------------
extern "C" void kernel_launch(void* const* d_in, const int* in_sizes, int n_in,
                              void* d_out, int out_size) {
    const float* img    = (const float*)d_in[0];
    const float* pooled = (const float*)d_in[1];
    const float* embed  = (const float*)d_in[2];
    const float* Wq     = (const float*)d_in[3];
    const float* bq     = (const float*)d_in[4];
    const float* Wk     = (const float*)d_in[5];
    const float* bk     = (const float*)d_in[6];
    const float* Wv     = (const float*)d_in[7];
    const float* bv     = (const float*)d_in[8];
    const float* Wih    = (const float*)d_in[9];
    const float* Whh    = (const float*)d_in[10];
    const float* bih    = (const float*)d_in[11];
    const float* bhh    = (const float*)d_in[12];
    const float* projW  = (const float*)d_in[13];
    const float* projb  = (const float*)d_in[14];
    const float* hattW  = (const float*)d_in[15];
    const float* hattb  = (const float*)d_in[16];
    const int*   sosp   = (const int*)d_in[17];
    float* out = (float*)d_out;

    dim3 tb(32, 8);
    transA<<<dim3(16, 64, 4), tb>>>(Wih, Whh);                               // 0
    transB<<<dim3(32, 313, 3), tb>>>(Wq, hattW, projW);                      // 1
    kvinit_kernel<<<dim3(32, 8), 256>>>(img, Wk, bk, Wv, bv, pooled, sosp);  // 2
    decode_loop<<<NB, NT>>>(embed, bih, bhh, projb, bq, hattb);              // 3 (abs idx 5)
    logits0_kernel<<<1250, 256>>>(embed, sosp, projW, projb);                // 4
    out_transpose<<<dim3(32, 79), 256>>>(out);                               // 5
    (void)in_sizes; (void)n_in; (void)out_size;
}